// round 9
// baseline (speedup 1.0000x reference)
#include <cuda_runtime.h>
#include <cstddef>

// Problem constants
#define BTOT   262144
#define NT     512          // threads per CTA
#define NROWS  128          // rows per pass
#define NPASS  (BTOT / NROWS)   // 2048
#define WSTR   68           // SMEM row stride in floats (16B-aligned, conflict-free)

// SMEM layout (floats)
// wf[3]:  wf[l][j*WSTR+k] = W_l[j][k+1]          (13056)
// wb[3]:  wb[l][k*WSTR+j] = W_l[j][k+1]          (13056)
// cv[3][64]: b_l[j] + t*W_l[j][0]  (folded; used by layer-2 fwd only)   (192)
// w0c[2][64]: W_l[j][0]   for layers 0,1 (ref-order forward)            (128)
// bia[2][64]: b_l[j]      for layers 0,1 (ref-order forward)            (128)
// bufA/bufB/bufE: [128][WSTR]                     (3*8704)
#define OFF_WB   13056
#define OFF_C    26112
#define OFF_W0C  26304
#define OFF_BIA  26432
#define OFF_A    26560
#define OFF_B    35264
#define OFF_E    43968
#define SMEM_FLOATS 52672
#define SMEM_BYTES  (SMEM_FLOATS * 4)   // 210,688 B

struct __align__(16) u64x2 { unsigned long long a, b; };

// packed fp32x2 FMA (exact fp32 per half)
__device__ __forceinline__ void ffma2(unsigned long long& d,
                                      unsigned long long x,
                                      unsigned long long y) {
    asm("fma.rn.f32x2 %0, %1, %2, %0;" : "+l"(d) : "l"(x), "l"(y));
}

__device__ __forceinline__ float redpair(unsigned long long v) {
    return __uint_as_float((unsigned)v) + __uint_as_float((unsigned)(v >> 32));
}

// Fast path (order-insensitive): o[jj] = (USE_C ? cv[j] : 0) + sum_k in[k]*M[j*WSTR+k]
template<bool USE_C>
__device__ __forceinline__ void gemv2x8(const float* __restrict__ M,
                                        const float* __restrict__ cv,
                                        const float* __restrict__ in0,
                                        const float* __restrict__ in1,
                                        int p, float o0[8], float o1[8]) {
    unsigned long long a0[8], a1[8];
#pragma unroll
    for (int jj = 0; jj < 8; jj++) {
        float cj = USE_C ? cv[p + 8 * jj] : 0.0f;
        a0[jj] = (unsigned long long)__float_as_uint(cj);
        a1[jj] = a0[jj];
    }
    const float* mrow = M + p * WSTR;
#pragma unroll 4
    for (int kb = 0; kb < 16; kb++) {
        const u64x2 h0 = *reinterpret_cast<const u64x2*>(in0 + 4 * kb);
        const u64x2 h1 = *reinterpret_cast<const u64x2*>(in1 + 4 * kb);
#pragma unroll
        for (int jj = 0; jj < 8; jj++) {
            const u64x2 wv =
                *reinterpret_cast<const u64x2*>(mrow + jj * (8 * WSTR) + 4 * kb);
            ffma2(a0[jj], h0.a, wv.a);
            ffma2(a0[jj], h0.b, wv.b);
            ffma2(a1[jj], h1.a, wv.a);
            ffma2(a1[jj], h1.b, wv.b);
        }
    }
#pragma unroll
    for (int jj = 0; jj < 8; jj++) {
        o0[jj] = redpair(a0[jj]);
        o1[jj] = redpair(a1[jj]);
    }
}

// Reference-order forward (mask-deciding layers): per output j, a single fp32
// FMA chain ascending k:  acc = fma(t, W[j][0], 0); acc = fma(h[k], W[j][k+1], acc)
// for k = 0..63 in order; then a = acc + b[j] as a separate final rounding.
// This reproduces XLA's (Eigen gebp / cutlass-SIMT sgemm) per-element
// accumulation order bit-for-bit, so ReLU mask decisions agree with the
// reference even for pre-activations within rounding noise of zero.
__device__ __forceinline__ void seqfwd2x8(const float* __restrict__ wk,
                                          const float* __restrict__ w0c,
                                          const float* __restrict__ bia,
                                          float t,
                                          const float* __restrict__ in0,
                                          const float* __restrict__ in1,
                                          int p, float a0[8], float a1[8]) {
    float c0[8], c1[8];
#pragma unroll
    for (int jj = 0; jj < 8; jj++) {
        float w0 = w0c[p + 8 * jj];
        c0[jj] = __fmaf_rn(t, w0, 0.0f);
        c1[jj] = c0[jj];
    }
    const float* mrow = wk + p * WSTR;
#pragma unroll 4
    for (int kb = 0; kb < 16; kb++) {
        const float4 h0 = *reinterpret_cast<const float4*>(in0 + 4 * kb);
        const float4 h1 = *reinterpret_cast<const float4*>(in1 + 4 * kb);
#pragma unroll
        for (int jj = 0; jj < 8; jj++) {
            const float4 wv =
                *reinterpret_cast<const float4*>(mrow + jj * (8 * WSTR) + 4 * kb);
            c0[jj] = __fmaf_rn(h0.x, wv.x, c0[jj]);
            c0[jj] = __fmaf_rn(h0.y, wv.y, c0[jj]);
            c0[jj] = __fmaf_rn(h0.z, wv.z, c0[jj]);
            c0[jj] = __fmaf_rn(h0.w, wv.w, c0[jj]);
            c1[jj] = __fmaf_rn(h1.x, wv.x, c1[jj]);
            c1[jj] = __fmaf_rn(h1.y, wv.y, c1[jj]);
            c1[jj] = __fmaf_rn(h1.z, wv.z, c1[jj]);
            c1[jj] = __fmaf_rn(h1.w, wv.w, c1[jj]);
        }
    }
#pragma unroll
    for (int jj = 0; jj < 8; jj++) {
        float bj = bia[p + 8 * jj];
        a0[jj] = c0[jj] + bj;
        a1[jj] = c1[jj] + bj;
    }
}

__global__ void __launch_bounds__(NT, 1)
ode_kernel(const float* __restrict__ gt, const float* __restrict__ gz,
           const float* __restrict__ ge,
           const float* __restrict__ W0, const float* __restrict__ b0,
           const float* __restrict__ W1, const float* __restrict__ b1,
           const float* __restrict__ W2, const float* __restrict__ b2,
           float* __restrict__ out) {
    extern __shared__ float sm[];
    float* wf   = sm;
    float* wb   = sm + OFF_WB;
    float* cv   = sm + OFF_C;
    float* w0c  = sm + OFF_W0C;
    float* bia  = sm + OFF_BIA;
    float* bufA = sm + OFF_A;
    float* bufB = sm + OFF_B;
    float* bufE = sm + OFF_E;

    const int tid = threadIdx.x;
    const float tval = gt[0];

    // ---- stage weights
    const float* Ws[3] = {W0, W1, W2};
#pragma unroll
    for (int l = 0; l < 3; l++) {
        const float* W = Ws[l];
        for (int idx = tid; idx < 64 * 64; idx += NT) {
            int j = idx >> 6, k = idx & 63;
            float w = W[j * 65 + k + 1];
            wf[l * 4352 + j * WSTR + k] = w;
            wb[l * 4352 + k * WSTR + j] = w;
        }
    }
    if (tid < 192) {
        int l = tid >> 6, j = tid & 63;
        const float* W  = Ws[l];
        const float* bb = (l == 0) ? b0 : (l == 1) ? b1 : b2;
        cv[tid] = bb[j] + tval * W[j * 65];
    }
    if (tid < 128) {
        int l = tid >> 6, j = tid & 63;
        const float* W  = l ? W1 : W0;
        w0c[tid] = W[j * 65];
        bia[tid] = l ? b1[j] : b0[j];
    }
    __syncthreads();

    const int p    = tid & 7;
    const int rp   = tid >> 3;
    const int r0   = rp * 2;
    const int r1   = r0 + 1;
    const int w    = tid >> 5;
    const int lane = tid & 31;

    float* A0 = bufA + r0 * WSTR;  float* A1 = bufA + r1 * WSTR;
    float* B0 = bufB + r0 * WSTR;  float* B1 = bufB + r1 * WSTR;
    float* E0 = bufE + r0 * WSTR;  float* E1 = bufE + r1 * WSTR;
    float* outD = out + (size_t)BTOT * 64;

    for (int tile = blockIdx.x; tile < NPASS; tile += gridDim.x) {
        const int rowBase = tile * NROWS;

        // ---- warp-local coalesced load: z -> bufA, e -> bufE
#pragma unroll
        for (int i = 0; i < 4; i++) {
            int q  = lane + 32 * i;
            int r  = q >> 4;
            int c4 = (q & 15) * 4;
            size_t gofs = (size_t)(rowBase + 8 * w + r) * 64 + c4;
            float4 zv = *reinterpret_cast<const float4*>(gz + gofs);
            *reinterpret_cast<float4*>(bufA + (8 * w + r) * WSTR + c4) = zv;
            float4 ev = *reinterpret_cast<const float4*>(ge + gofs);
            *reinterpret_cast<float4*>(bufE + (8 * w + r) * WSTR + c4) = ev;
        }
        __syncwarp();

        float o0[8], o1[8];
        unsigned m0a = 0, m0b = 0, m1a = 0, m1b = 0;

        // ---- forward layer 0 (ref-order): z(A) -> h0(B), record masks
        seqfwd2x8(wf, w0c, bia, tval, A0, A1, p, o0, o1);
#pragma unroll
        for (int jj = 0; jj < 8; jj++) {
            m0a |= (unsigned)(o0[jj] > 0.0f) << jj;
            m0b |= (unsigned)(o1[jj] > 0.0f) << jj;
            B0[p + 8 * jj] = fmaxf(o0[jj], 0.0f);
            B1[p + 8 * jj] = fmaxf(o1[jj], 0.0f);
        }
        __syncwarp();

        // ---- forward layer 1 (ref-order): h0(B) -> h1(A), record masks
        seqfwd2x8(wf + 4352, w0c + 64, bia + 64, tval, B0, B1, p, o0, o1);
#pragma unroll
        for (int jj = 0; jj < 8; jj++) {
            m1a |= (unsigned)(o0[jj] > 0.0f) << jj;
            m1b |= (unsigned)(o1[jj] > 0.0f) << jj;
            A0[p + 8 * jj] = fmaxf(o0[jj], 0.0f);
            A1[p + 8 * jj] = fmaxf(o1[jj], 0.0f);
        }
        __syncwarp();

        // ---- forward layer 2 (no relu, fast path): h1(A) -> z_dot(B)
        gemv2x8<true>(wf + 8704, cv + 128, A0, A1, p, o0, o1);
#pragma unroll
        for (int jj = 0; jj < 8; jj++) {
            B0[p + 8 * jj] = o0[jj];
            B1[p + 8 * jj] = o1[jj];
        }
        __syncwarp();

        // ---- flush z_dot (coalesced)
#pragma unroll
        for (int i = 0; i < 4; i++) {
            int q  = lane + 32 * i;
            int r  = q >> 4;
            int c4 = (q & 15) * 4;
            float4 v = *reinterpret_cast<const float4*>(bufB + (8 * w + r) * WSTR + c4);
            *reinterpret_cast<float4*>(out + (size_t)(rowBase + 8 * w + r) * 64 + c4) = v;
        }

        // ---- backward layer 2: g1 = W2[:,1:]^T e, mask by h1  (E -> A)
        gemv2x8<false>(wb + 8704, cv, E0, E1, p, o0, o1);
#pragma unroll
        for (int jj = 0; jj < 8; jj++) {
            A0[p + 8 * jj] = ((m1a >> jj) & 1) ? o0[jj] : 0.0f;
            A1[p + 8 * jj] = ((m1b >> jj) & 1) ? o1[jj] : 0.0f;
        }
        __syncwarp();

        // ---- backward layer 1: g0 = W1[:,1:]^T g1, mask by h0  (A -> B)
        gemv2x8<false>(wb + 4352, cv, A0, A1, p, o0, o1);
#pragma unroll
        for (int jj = 0; jj < 8; jj++) {
            B0[p + 8 * jj] = ((m0a >> jj) & 1) ? o0[jj] : 0.0f;
            B1[p + 8 * jj] = ((m0b >> jj) & 1) ? o1[jj] : 0.0f;
        }
        __syncwarp();

        // ---- backward layer 0: gz = W0[:,1:]^T g0, then div = <gz, e>
        gemv2x8<false>(wb, cv, B0, B1, p, o0, o1);
        float d0 = 0.0f, d1 = 0.0f;
#pragma unroll
        for (int jj = 0; jj < 8; jj++) {
            d0 += o0[jj] * E0[p + 8 * jj];
            d1 += o1[jj] * E1[p + 8 * jj];
        }
        d0 += __shfl_down_sync(0xffffffffu, d0, 4, 8);
        d0 += __shfl_down_sync(0xffffffffu, d0, 2, 8);
        d0 += __shfl_down_sync(0xffffffffu, d0, 1, 8);
        d1 += __shfl_down_sync(0xffffffffu, d1, 4, 8);
        d1 += __shfl_down_sync(0xffffffffu, d1, 2, 8);
        d1 += __shfl_down_sync(0xffffffffu, d1, 1, 8);
        if (p == 0) {
            outD[rowBase + r0] = -d0;
            outD[rowBase + r1] = -d1;
        }
        __syncwarp();
    }
}

extern "C" void kernel_launch(void* const* d_in, const int* in_sizes, int n_in,
                              void* d_out, int out_size) {
    // metadata order: t, z, e, W0, b0, W1, b1, W2, b2 (all float32)
    const float* t  = (const float*)d_in[0];
    const float* z  = (const float*)d_in[1];
    const float* e  = (const float*)d_in[2];
    const float* W0 = (const float*)d_in[3];
    const float* b0 = (const float*)d_in[4];
    const float* W1 = (const float*)d_in[5];
    const float* b1 = (const float*)d_in[6];
    const float* W2 = (const float*)d_in[7];
    const float* b2 = (const float*)d_in[8];
    float* out = (float*)d_out;   // [B*64] z_dot followed by [B] of -div

    (void)in_sizes; (void)n_in; (void)out_size;

    cudaFuncSetAttribute(ode_kernel,
                         cudaFuncAttributeMaxDynamicSharedMemorySize, SMEM_BYTES);

    int dev = 0;
    cudaGetDevice(&dev);
    int sms = 148;
    cudaDeviceGetAttribute(&sms, cudaDevAttrMultiProcessorCount, dev);
    if (sms < 1) sms = 148;
    if (sms > NPASS) sms = NPASS;

    ode_kernel<<<sms, NT, SMEM_BYTES>>>(t, z, e, W0, b0, W1, b1, W2, b2, out);
}

// round 11
// speedup vs baseline: 1.3502x; 1.3502x over previous
#include <cuda_runtime.h>
#include <cstddef>

// Problem constants
#define BTOT   262144
#define NT     256          // threads per CTA (8 warps)
#define NROWS  128          // rows per tile (32 groups of 8 threads x 4 rows)
#define NPASS  (BTOT / NROWS)   // 2048
#define WSTR   68           // weight SMEM row stride in floats (16B aligned, conflict-free)

// SMEM layout (floats)
// wf[3]:  wf[l][j*WSTR+k] = W_l[j][k+1]     forward, slot-major      (13056)
// wb[3]:  wb[l][k*WSTR+j] = W_l[j][k+1]     backward (transposed)    (13056)
// cv[3][64]: b + t*W[:,0] folded (used by fwd layer 2)               (192)
// w0c[2][64]: W_l[j][0]  for seq layers 0,1                          (128)
// bia[2][64]: b_l[j]     for seq layers 0,1                          (128)
// bufA/bufB/bufE: INTERLEAVED row-pair buffers: [64 pairs][64 k][2]  (3*8192)
#define OFF_WB   13056
#define OFF_C    26112
#define OFF_W0C  26304
#define OFF_BIA  26432
#define OFF_A    26560
#define OFF_B    34752
#define OFF_E    42944
#define SMEM_FLOATS 51136
#define SMEM_BYTES  (SMEM_FLOATS * 4)   // 204,544 B

typedef unsigned long long ull;
struct __align__(16) u64x2 { ull a, b; };

// packed fp32x2 FMA: two INDEPENDENT IEEE fp32 fma ops (lo, hi halves).
// With halves = (row_i, row_{i+1}), each half is a bit-exact sequential chain.
__device__ __forceinline__ void ffma2(ull& d, ull x, ull y) {
    asm("fma.rn.f32x2 %0, %1, %2, %0;" : "+l"(d) : "l"(x), "l"(y));
}
__device__ __forceinline__ ull addf2(ull a, ull b) {
    ull r; asm("add.rn.f32x2 %0, %1, %2;" : "=l"(r) : "l"(a), "l"(b)); return r;
}
__device__ __forceinline__ ull splat2(float f) {
    ull r; asm("mov.b64 %0, {%1, %1};" : "=l"(r) : "f"(f)); return r;
}
__device__ __forceinline__ ull pk(float lo, float hi) {
    ull r; asm("mov.b64 %0, {%1, %2};" : "=l"(r) : "f"(lo), "f"(hi)); return r;
}
__device__ __forceinline__ void unpk(ull v, float& lo, float& hi) {
    asm("mov.b64 {%0, %1}, %2;" : "=f"(lo), "=f"(hi) : "l"(v));
}

// Row-pair GEMV: for this thread's 8 slots s = p + 8*jj, for 2 row-pairs
// (aq0 = rows r0,r1 interleaved; aq1 = rows r2,r3):
//   acc[jj].half = init[jj].half + sum_{k ascending} a[k]*M[s*WSTR+k]
// Strictly sequential per half -> reference accumulation order preserved.
__device__ __forceinline__ void gemv_pair(const float* __restrict__ M,
                                          const float* __restrict__ aq0,
                                          const float* __restrict__ aq1,
                                          int p, const ull init[8],
                                          ull acc0[8], ull acc1[8]) {
#pragma unroll
    for (int jj = 0; jj < 8; jj++) { acc0[jj] = init[jj]; acc1[jj] = init[jj]; }
    const float* mrow = M + p * WSTR;
#pragma unroll 4
    for (int kb = 0; kb < 16; kb++) {
        const u64x2 h0a = *reinterpret_cast<const u64x2*>(aq0 + 8 * kb);      // k, k+1
        const u64x2 h0b = *reinterpret_cast<const u64x2*>(aq0 + 8 * kb + 4);  // k+2, k+3
        const u64x2 h1a = *reinterpret_cast<const u64x2*>(aq1 + 8 * kb);
        const u64x2 h1b = *reinterpret_cast<const u64x2*>(aq1 + 8 * kb + 4);
#pragma unroll
        for (int jj = 0; jj < 8; jj++) {
            const float4 wv =
                *reinterpret_cast<const float4*>(mrow + jj * (8 * WSTR) + 4 * kb);
            ull wx = splat2(wv.x), wy = splat2(wv.y);
            ull wz = splat2(wv.z), ww = splat2(wv.w);
            ffma2(acc0[jj], h0a.a, wx);
            ffma2(acc0[jj], h0a.b, wy);
            ffma2(acc0[jj], h0b.a, wz);
            ffma2(acc0[jj], h0b.b, ww);
            ffma2(acc1[jj], h1a.a, wx);
            ffma2(acc1[jj], h1a.b, wy);
            ffma2(acc1[jj], h1b.a, wz);
            ffma2(acc1[jj], h1b.b, ww);
        }
    }
}

__global__ void __launch_bounds__(NT, 1)
ode_kernel(const float* __restrict__ gt, const float* __restrict__ gz,
           const float* __restrict__ ge,
           const float* __restrict__ W0, const float* __restrict__ b0,
           const float* __restrict__ W1, const float* __restrict__ b1,
           const float* __restrict__ W2, const float* __restrict__ b2,
           float* __restrict__ out) {
    extern __shared__ float sm[];
    float* wf   = sm;
    float* wb   = sm + OFF_WB;
    float* cv   = sm + OFF_C;
    float* w0c  = sm + OFF_W0C;
    float* bia  = sm + OFF_BIA;
    float* bufA = sm + OFF_A;
    float* bufB = sm + OFF_B;
    float* bufE = sm + OFF_E;

    const int tid = threadIdx.x;
    const float tval = gt[0];

    // ---- stage weights
    const float* Ws[3] = {W0, W1, W2};
#pragma unroll
    for (int l = 0; l < 3; l++) {
        const float* W = Ws[l];
        for (int idx = tid; idx < 64 * 64; idx += NT) {
            int j = idx >> 6, k = idx & 63;
            float wgt = W[j * 65 + k + 1];
            wf[l * 4352 + j * WSTR + k] = wgt;
            wb[l * 4352 + k * WSTR + j] = wgt;
        }
    }
    if (tid < 192) {
        int l = tid >> 6, j = tid & 63;
        const float* W  = Ws[l];
        const float* bb = (l == 0) ? b0 : (l == 1) ? b1 : b2;
        cv[tid] = bb[j] + tval * W[j * 65];
    }
    if (tid < 128) {
        int l = tid >> 6, j = tid & 63;
        const float* W  = l ? W1 : W0;
        w0c[tid] = W[j * 65];
        bia[tid] = l ? b1[j] : b0[j];
    }
    __syncthreads();

    const int p    = tid & 7;        // output slot within group
    const int g    = tid >> 3;       // group id (0..31), owns rows 4g..4g+3
    const int q0   = 2 * g;          // pair 0 = rows 4g, 4g+1
    const int q1   = 2 * g + 1;      // pair 1 = rows 4g+2, 4g+3
    const int w    = tid >> 5;       // warp id (owns rows 16w..16w+15 = pairs 8w..8w+7)
    const int lane = tid & 31;

    const float* A0 = bufA + q0 * 128;  const float* A1 = bufA + q1 * 128;
    const float* B0 = bufB + q0 * 128;  const float* B1 = bufB + q1 * 128;
    const float* E0 = bufE + q0 * 128;  const float* E1 = bufE + q1 * 128;
    float* outD = out + (size_t)BTOT * 64;

    for (int tile = blockIdx.x; tile < NPASS; tile += gridDim.x) {
        const int rowBase = tile * NROWS;

        // ---- stage z -> bufA, e -> bufE, interleaved by row pair (warp-local)
#pragma unroll
        for (int it = 0; it < 4; it++) {
            const int pairI = w * 8 + it * 2 + (lane >> 4);
            const int c     = lane & 15;
            const size_t g0 = (size_t)(rowBase + 2 * pairI) * 64 + 4 * c;
            float4 za = *reinterpret_cast<const float4*>(gz + g0);
            float4 zb = *reinterpret_cast<const float4*>(gz + g0 + 64);
            u64x2 v1, v2;
            v1.a = pk(za.x, zb.x); v1.b = pk(za.y, zb.y);
            v2.a = pk(za.z, zb.z); v2.b = pk(za.w, zb.w);
            *reinterpret_cast<u64x2*>(bufA + pairI * 128 + 8 * c)     = v1;
            *reinterpret_cast<u64x2*>(bufA + pairI * 128 + 8 * c + 4) = v2;
            float4 ea = *reinterpret_cast<const float4*>(ge + g0);
            float4 eb = *reinterpret_cast<const float4*>(ge + g0 + 64);
            v1.a = pk(ea.x, eb.x); v1.b = pk(ea.y, eb.y);
            v2.a = pk(ea.z, eb.z); v2.b = pk(ea.w, eb.w);
            *reinterpret_cast<u64x2*>(bufE + pairI * 128 + 8 * c)     = v1;
            *reinterpret_cast<u64x2*>(bufE + pairI * 128 + 8 * c + 4) = v2;
        }
        __syncwarp();

        ull init[8], a0[8], a1[8];
        unsigned m0q0 = 0, m0q1 = 0, m1q0 = 0, m1q1 = 0;

        // ---- forward layer 0 (ref-order per half): z(A) -> h0(B), masks m0
#pragma unroll
        for (int jj = 0; jj < 8; jj++)
            init[jj] = splat2(__fmaf_rn(tval, w0c[p + 8 * jj], 0.0f));
        gemv_pair(wf, A0, A1, p, init, a0, a1);
#pragma unroll
        for (int jj = 0; jj < 8; jj++) {
            ull bsp = splat2(bia[p + 8 * jj]);
            float lo, hi;
            unpk(addf2(a0[jj], bsp), lo, hi);
            m0q0 |= ((lo > 0.0f) ? 1u : 0u) << jj;
            m0q0 |= ((hi > 0.0f) ? 1u : 0u) << (jj + 8);
            *reinterpret_cast<ull*>(bufB + q0 * 128 + 2 * (p + 8 * jj)) =
                pk(fmaxf(lo, 0.0f), fmaxf(hi, 0.0f));
            unpk(addf2(a1[jj], bsp), lo, hi);
            m0q1 |= ((lo > 0.0f) ? 1u : 0u) << jj;
            m0q1 |= ((hi > 0.0f) ? 1u : 0u) << (jj + 8);
            *reinterpret_cast<ull*>(bufB + q1 * 128 + 2 * (p + 8 * jj)) =
                pk(fmaxf(lo, 0.0f), fmaxf(hi, 0.0f));
        }
        __syncwarp();

        // ---- forward layer 1 (ref-order per half): h0(B) -> h1(A), masks m1
#pragma unroll
        for (int jj = 0; jj < 8; jj++)
            init[jj] = splat2(__fmaf_rn(tval, w0c[64 + p + 8 * jj], 0.0f));
        gemv_pair(wf + 4352, B0, B1, p, init, a0, a1);
#pragma unroll
        for (int jj = 0; jj < 8; jj++) {
            ull bsp = splat2(bia[64 + p + 8 * jj]);
            float lo, hi;
            unpk(addf2(a0[jj], bsp), lo, hi);
            m1q0 |= ((lo > 0.0f) ? 1u : 0u) << jj;
            m1q0 |= ((hi > 0.0f) ? 1u : 0u) << (jj + 8);
            *reinterpret_cast<ull*>(bufA + q0 * 128 + 2 * (p + 8 * jj)) =
                pk(fmaxf(lo, 0.0f), fmaxf(hi, 0.0f));
            unpk(addf2(a1[jj], bsp), lo, hi);
            m1q1 |= ((lo > 0.0f) ? 1u : 0u) << jj;
            m1q1 |= ((hi > 0.0f) ? 1u : 0u) << (jj + 8);
            *reinterpret_cast<ull*>(bufA + q1 * 128 + 2 * (p + 8 * jj)) =
                pk(fmaxf(lo, 0.0f), fmaxf(hi, 0.0f));
        }
        __syncwarp();

        // ---- forward layer 2 (no relu): h1(A) -> z_dot(B)
#pragma unroll
        for (int jj = 0; jj < 8; jj++)
            init[jj] = splat2(cv[128 + p + 8 * jj]);
        gemv_pair(wf + 8704, A0, A1, p, init, a0, a1);
#pragma unroll
        for (int jj = 0; jj < 8; jj++) {
            *reinterpret_cast<ull*>(bufB + q0 * 128 + 2 * (p + 8 * jj)) = a0[jj];
            *reinterpret_cast<ull*>(bufB + q1 * 128 + 2 * (p + 8 * jj)) = a1[jj];
        }
        __syncwarp();

        // ---- flush z_dot: deinterleave B -> global (coalesced)
#pragma unroll
        for (int it = 0; it < 4; it++) {
            const int pairI = w * 8 + it * 2 + (lane >> 4);
            const int c     = lane & 15;
            u64x2 v1 = *reinterpret_cast<const u64x2*>(bufB + pairI * 128 + 8 * c);
            u64x2 v2 = *reinterpret_cast<const u64x2*>(bufB + pairI * 128 + 8 * c + 4);
            float4 ra, rb;
            unpk(v1.a, ra.x, rb.x); unpk(v1.b, ra.y, rb.y);
            unpk(v2.a, ra.z, rb.z); unpk(v2.b, ra.w, rb.w);
            const size_t g0 = (size_t)(rowBase + 2 * pairI) * 64 + 4 * c;
            *reinterpret_cast<float4*>(out + g0)      = ra;
            *reinterpret_cast<float4*>(out + g0 + 64) = rb;
        }

        // ---- backward layer 2: g1 = W2[:,1:]^T e, mask m1  (E -> A)
#pragma unroll
        for (int jj = 0; jj < 8; jj++) init[jj] = 0ull;
        gemv_pair(wb + 8704, E0, E1, p, init, a0, a1);
#pragma unroll
        for (int jj = 0; jj < 8; jj++) {
            float lo, hi;
            unpk(a0[jj], lo, hi);
            lo = ((m1q0 >> jj) & 1) ? lo : 0.0f;
            hi = ((m1q0 >> (jj + 8)) & 1) ? hi : 0.0f;
            *reinterpret_cast<ull*>(bufA + q0 * 128 + 2 * (p + 8 * jj)) = pk(lo, hi);
            unpk(a1[jj], lo, hi);
            lo = ((m1q1 >> jj) & 1) ? lo : 0.0f;
            hi = ((m1q1 >> (jj + 8)) & 1) ? hi : 0.0f;
            *reinterpret_cast<ull*>(bufA + q1 * 128 + 2 * (p + 8 * jj)) = pk(lo, hi);
        }
        __syncwarp();

        // ---- backward layer 1: g0 = W1[:,1:]^T g1, mask m0  (A -> B)
        gemv_pair(wb + 4352, A0, A1, p, init, a0, a1);
#pragma unroll
        for (int jj = 0; jj < 8; jj++) {
            float lo, hi;
            unpk(a0[jj], lo, hi);
            lo = ((m0q0 >> jj) & 1) ? lo : 0.0f;
            hi = ((m0q0 >> (jj + 8)) & 1) ? hi : 0.0f;
            *reinterpret_cast<ull*>(bufB + q0 * 128 + 2 * (p + 8 * jj)) = pk(lo, hi);
            unpk(a1[jj], lo, hi);
            lo = ((m0q1 >> jj) & 1) ? lo : 0.0f;
            hi = ((m0q1 >> (jj + 8)) & 1) ? hi : 0.0f;
            *reinterpret_cast<ull*>(bufB + q1 * 128 + 2 * (p + 8 * jj)) = pk(lo, hi);
        }
        __syncwarp();

        // ---- backward layer 0: gz = W0[:,1:]^T g0, then div = <gz, e>
        gemv_pair(wb, B0, B1, p, init, a0, a1);
        ull dq0 = 0ull, dq1 = 0ull;
#pragma unroll
        for (int jj = 0; jj < 8; jj++) {
            ffma2(dq0, a0[jj],
                  *reinterpret_cast<const ull*>(bufE + q0 * 128 + 2 * (p + 8 * jj)));
            ffma2(dq1, a1[jj],
                  *reinterpret_cast<const ull*>(bufE + q1 * 128 + 2 * (p + 8 * jj)));
        }
        float d0, d1, d2, d3;
        unpk(dq0, d0, d1);
        unpk(dq1, d2, d3);
#pragma unroll
        for (int ofs = 4; ofs > 0; ofs >>= 1) {
            d0 += __shfl_down_sync(0xffffffffu, d0, ofs, 8);
            d1 += __shfl_down_sync(0xffffffffu, d1, ofs, 8);
            d2 += __shfl_down_sync(0xffffffffu, d2, ofs, 8);
            d3 += __shfl_down_sync(0xffffffffu, d3, ofs, 8);
        }
        if (p == 0) {
            outD[rowBase + 4 * g + 0] = -d0;
            outD[rowBase + 4 * g + 1] = -d1;
            outD[rowBase + 4 * g + 2] = -d2;
            outD[rowBase + 4 * g + 3] = -d3;
        }
        __syncwarp();
    }
}

extern "C" void kernel_launch(void* const* d_in, const int* in_sizes, int n_in,
                              void* d_out, int out_size) {
    // metadata order: t, z, e, W0, b0, W1, b1, W2, b2 (all float32)
    const float* t  = (const float*)d_in[0];
    const float* z  = (const float*)d_in[1];
    const float* e  = (const float*)d_in[2];
    const float* W0 = (const float*)d_in[3];
    const float* b0 = (const float*)d_in[4];
    const float* W1 = (const float*)d_in[5];
    const float* b1 = (const float*)d_in[6];
    const float* W2 = (const float*)d_in[7];
    const float* b2 = (const float*)d_in[8];
    float* out = (float*)d_out;   // [B*64] z_dot followed by [B] of -div

    (void)in_sizes; (void)n_in; (void)out_size;

    cudaFuncSetAttribute(ode_kernel,
                         cudaFuncAttributeMaxDynamicSharedMemorySize, SMEM_BYTES);

    int dev = 0;
    cudaGetDevice(&dev);
    int sms = 148;
    cudaDeviceGetAttribute(&sms, cudaDevAttrMultiProcessorCount, dev);
    if (sms < 1) sms = 148;
    if (sms > NPASS) sms = NPASS;

    ode_kernel<<<sms, NT, SMEM_BYTES>>>(t, z, e, W0, b0, W1, b1, W2, b2, out);
}